// round 15
// baseline (speedup 1.0000x reference)
#include <cuda_runtime.h>
#include <cuda_fp16.h>
#include <cstdint>

#define LVAL 4096
#define NB 64
#define NROWS 16384            // 32*512
#define PW 36                  // padded row stride in u32 words (32 data words + 4 pad)
#define RADIUS 0.9
#define KSPLIT 8

// ---------------- device globals (no allocs allowed) ----------------
__device__ __half g_Bh [NB * LVAL];    // Blaschke hi split, [n][l] l-contig
__device__ __half g_Bl [NB * LVAL];    // lo split
__device__ __half g_BTh[LVAL * NB];    // transposed (plain fp16 B for attn GEMM)
__device__ float  g_proj[KSPLIT * NROWS * NB];   // split-K partial projections
__device__ __half g_W0[NROWS * NB];    // softmax weights hi split, [row][n]
__device__ __half g_W1[NROWS * NB];    // lo split

// ---------------- helpers ----------------
__device__ __forceinline__ unsigned smem_u32p(const void* p) {
    return (unsigned)__cvta_generic_to_shared(p);
}
__device__ __forceinline__ void cp16(unsigned dst, const void* src) {
    asm volatile("cp.async.ca.shared.global [%0], [%1], 16;\n" :: "r"(dst), "l"(src));
}
__device__ __forceinline__ void cp_commit() {
    asm volatile("cp.async.commit_group;\n" ::: "memory");
}
template <int N>
__device__ __forceinline__ void cp_wait() {
    asm volatile("cp.async.wait_group %0;\n" :: "n"(N) : "memory");
}
__device__ __forceinline__ uint32_t packh(__half a, __half b) {
    __half2 h = __halves2half2(a, b);
    return *reinterpret_cast<uint32_t*>(&h);
}
__device__ __forceinline__ uint32_t pack_rn(float a, float b) {
    return packh(__float2half_rn(a), __float2half_rn(b));
}

// D(16x8) += A(16x16) * B(16x8), fp16 inputs, fp32 accum
__device__ __forceinline__ void mma16(float* c, const uint32_t* a, const uint32_t* b) {
    asm volatile(
        "mma.sync.aligned.m16n8k16.row.col.f32.f16.f16.f32 "
        "{%0,%1,%2,%3}, {%4,%5,%6,%7}, {%8,%9}, {%0,%1,%2,%3};\n"
        : "+f"(c[0]), "+f"(c[1]), "+f"(c[2]), "+f"(c[3])
        : "r"(a[0]), "r"(a[1]), "r"(a[2]), "r"(a[3]),
          "r"(b[0]), "r"(b[1]));
}

__device__ __forceinline__ void ldsm_x4(uint32_t* r, uint32_t addr) {
    asm volatile("ldmatrix.sync.aligned.m8n8.x4.shared.b16 {%0,%1,%2,%3}, [%4];"
        : "=r"(r[0]), "=r"(r[1]), "=r"(r[2]), "=r"(r[3]) : "r"(addr));
}

// ---------------- k1: build Blaschke basis + fp16 splits ----------------
__global__ void k1_build() {
    int idx = blockIdx.x * blockDim.x + threadIdx.x;
    if (idx >= NB * LVAL) return;
    int n = idx >> 12;
    int l = idx & 4095;
    const double TWO_PI = 6.283185307179586476925286766559;
    double theta = (double)n * (TWO_PI / 64.0);
    double t     = (double)l * (TWO_PI / 4095.0);   // linspace(0,2pi,4096) incl. endpoint
    float c = cosf((float)(t - theta));             // arg exact in double, cos in fp32
    const float r = (float)RADIUS;
    float v = sqrtf(1.0f - r * r) * (1.0f - r * c) / (1.0f - 2.0f * r * c + r * r);
    __half h = __float2half_rn(v);
    __half lo = __float2half_rn(v - __half2float(h));
    g_Bh [n * LVAL + l] = h;
    g_Bl [n * LVAL + l] = lo;
    g_BTh[l * NB + n]   = h;
}

// ---------------- k2: proj slab GEMM  (split-K = 8, 64-row CTA, 3 CTA/SM) ----
// CTA: 64 rows x 64 basis, K-slice 512, 8 chunks of 64, double-buffered, pipelined.
// stage layout (u32 words): xh[0,2304) xl[2304,4608) bh[4608,6912) bl[6912,9216)
#define K2_STAGE 9216
#define K2_SMEM_BYTES (2 * K2_STAGE * 4)   // 73728

__global__ __launch_bounds__(256, 3) void k2_proj(const float* __restrict__ x) {
    extern __shared__ uint32_t smu[];
    const int tid = threadIdx.x, warp = tid >> 5, lane = tid & 31;
    const int g = lane >> 2, tig = lane & 3;
    const int r0 = blockIdx.x * 64;
    const int kslab = blockIdx.y * (LVAL / KSPLIT);   // 512
    const int rw = (warp & 3) * 16;      // warp x-row offset (A operand, m)
    const int nw = (warp >> 2) * 32;     // warp basis offset (B operand, n)
    const int quad = tid & 15, rloc = tid >> 4;

    const int arow   = lane & 15;
    const int acol16 = (lane >> 4) & 1;
    const int brow   = lane & 7;
    const int bcol16 = (lane >> 3) & 1;
    const int bpair  = (lane >> 4) & 1;

    float acc[4][4];
    #pragma unroll
    for (int i = 0; i < 4; i++)
        #pragma unroll
        for (int j = 0; j < 4; j++) acc[i][j] = 0.f;

    auto ldg_x = [&](int c, float4* xr) {
        const int kbase = kslab + c * 64;
        #pragma unroll
        for (int i = 0; i < 4; i++) {
            int row = rloc + i * 16;
            xr[i] = *(const float4*)(x + (size_t)(r0 + row) * LVAL + kbase + quad * 4);
        }
    };
    auto cvt_sts_x = [&](int c, const float4* xr) {
        uint32_t* b = smu + (c & 1) * K2_STAGE;
        #pragma unroll
        for (int i = 0; i < 4; i++) {
            int row = rloc + i * 16;
            const float4 v = xr[i];
            __half hx = __float2half_rn(v.x), hy = __float2half_rn(v.y);
            __half hz = __float2half_rn(v.z), hw = __float2half_rn(v.w);
            uint32_t h01 = packh(hx, hy), h23 = packh(hz, hw);
            uint32_t l01 = pack_rn(v.x - __half2float(hx), v.y - __half2float(hy));
            uint32_t l23 = pack_rn(v.z - __half2float(hz), v.w - __half2float(hw));
            *(uint2*)(b + row * PW + quad * 2)        = make_uint2(h01, h23);
            *(uint2*)(b + 2304 + row * PW + quad * 2) = make_uint2(l01, l23);
        }
    };
    auto cp_B = [&](int c) {
        uint32_t* b = smu + (c & 1) * K2_STAGE;
        const int kbase = kslab + c * 64;
        #pragma unroll
        for (int j = 0; j < 2; j++) {
            int e = tid + j * 256; int n = e >> 3, seg = e & 7;
            cp16(smem_u32p(b + 4608 + n * PW + seg * 4),
                 g_Bh + (size_t)n * LVAL + kbase + seg * 8);
            cp16(smem_u32p(b + 6912 + n * PW + seg * 4),
                 g_Bl + (size_t)n * LVAL + kbase + seg * 8);
        }
        cp_commit();
    };

    float4 xr[4];
    // prologue: B0 in flight; x0 converted; x1 loaded into regs
    cp_B(0);
    ldg_x(0, xr);
    cvt_sts_x(0, xr);
    ldg_x(1, xr);

    for (int c = 0; c < KSPLIT; c++) {
        cp_wait<0>();          // B_c landed
        __syncthreads();       // orders STS x_c + frees buffer (c+1)&1
        if (c + 1 < KSPLIT) cp_B(c + 1);   // overlaps mma(c)

        const uint32_t* buf = smu + (c & 1) * K2_STAGE;
        const uint32_t aHi = smem_u32p(buf +        (rw + arow) * PW) + acol16 * 16;
        const uint32_t aLo = smem_u32p(buf + 2304 + (rw + arow) * PW) + acol16 * 16;
        const uint32_t bHi = smem_u32p(buf + 4608 + (nw + bpair * 8 + brow) * PW) + bcol16 * 16;
        const uint32_t bLo = smem_u32p(buf + 6912 + (nw + bpair * 8 + brow) * PW) + bcol16 * 16;

        #pragma unroll
        for (int ks = 0; ks < 4; ks++) {
            const int kb = ks * 32;
            uint32_t ah[4], al[4], bh[2][4], bl[2][4];
            ldsm_x4(ah, aHi + kb);
            ldsm_x4(al, aLo + kb);
            #pragma unroll
            for (int p = 0; p < 2; p++) {
                ldsm_x4(bh[p], bHi + p * (16 * PW * 4) + kb);
                ldsm_x4(bl[p], bLo + p * (16 * PW * 4) + kb);
            }
            #pragma unroll
            for (int nt = 0; nt < 4; nt++) {
                const int p = nt >> 1, o = (nt & 1) * 2;
                mma16(acc[nt], ah, &bh[p][o]);
                mma16(acc[nt], ah, &bl[p][o]);
                mma16(acc[nt], al, &bh[p][o]);
            }
        }

        if (c + 1 < KSPLIT) {
            cvt_sts_x(c + 1, xr);                   // regs loaded last iteration
            if (c + 2 < KSPLIT) ldg_x(c + 2, xr);   // hidden behind next mma
        }
    }

    float* slab = g_proj + (size_t)blockIdx.y * (NROWS * NB);
    #pragma unroll
    for (int nt = 0; nt < 4; nt++) {
        int col = nw + nt * 8 + 2 * tig;
        int row = r0 + rw + g;
        *(float2*)(slab + (size_t)row * NB + col)       = make_float2(acc[nt][0], acc[nt][1]);
        *(float2*)(slab + (size_t)(row + 8) * NB + col) = make_float2(acc[nt][2], acc[nt][3]);
    }
}

// ---------------- k3: reduce slabs + softmax(|.|) + fp16 W split ----------------
__global__ __launch_bounds__(256) void k3_softmax() {
    const int warp = threadIdx.x >> 5, lane = threadIdx.x & 31;
    const int row = blockIdx.x * 8 + warp;
    const size_t base = (size_t)row * NB + 2 * lane;
    float p0 = 0.f, p1 = 0.f;
    #pragma unroll
    for (int s = 0; s < KSPLIT; s++) {
        float2 v = *(const float2*)(g_proj + (size_t)s * (NROWS * NB) + base);
        p0 += v.x; p1 += v.y;
    }
    float a0 = fabsf(p0), a1 = fabsf(p1);
    float m = fmaxf(a0, a1);
    #pragma unroll
    for (int o = 16; o > 0; o >>= 1) m = fmaxf(m, __shfl_xor_sync(0xffffffffu, m, o));
    float e0 = __expf(a0 - m), e1 = __expf(a1 - m);
    float s = e0 + e1;
    #pragma unroll
    for (int o = 16; o > 0; o >>= 1) s += __shfl_xor_sync(0xffffffffu, s, o);
    float inv = 1.0f / s;
    float w0 = e0 * inv, w1 = e1 * inv;
    __half h0 = __float2half_rn(w0), h1 = __float2half_rn(w1);
    *(uint32_t*)&g_W0[base] = packh(h0, h1);
    *(uint32_t*)&g_W1[base] = pack_rn(w0 - __half2float(h0), w1 - __half2float(h1));
}

// ---------------- k4: out = x + W*B  (64 rows x 128 l per CTA, 2-term) ----------------
// attn = (Wh + Wl) * Bh ; W split exact, B plain fp16 (validated rel_err 1.28e-4, 92.7us)
// smem (u32 words): Wh[0,2304) Wl[2304,4608) BTh[4608,9216)
// epilogue reuses smem as fp32 attn staging [64][132] (8448 words < 9216)
#define K4_SMEM_WORDS 9216
#define K4_SMEM_BYTES (K4_SMEM_WORDS * 4)   // 36864
#define SE 132                 // epilogue staging stride (floats)

__global__ __launch_bounds__(256, 4) void k4_attn(
    const float* __restrict__ x, float* __restrict__ out)
{
    extern __shared__ uint32_t smu[];
    const int tid = threadIdx.x, warp = tid >> 5, lane = tid & 31;
    const int g = lane >> 2, tig = lane & 3;
    const int r0 = blockIdx.y * 64;
    const int l0 = blockIdx.x * 128;
    const int rw = (warp & 1) * 32;      // warp row offset (2 groups of 32)
    const int lw = (warp >> 1) * 32;     // warp l offset   (4 groups of 32)

    // -------- stage W hi/lo (64 rows) and BTh (128 rows) via cp.async --------
    #pragma unroll
    for (int j = 0; j < 2; j++) {
        int e = tid + j * 256; int row = e >> 3, seg = e & 7;
        cp16(smem_u32p(smu + 0    + row * PW + seg * 4), g_W0 + (size_t)(r0 + row) * NB + seg * 8);
        cp16(smem_u32p(smu + 2304 + row * PW + seg * 4), g_W1 + (size_t)(r0 + row) * NB + seg * 8);
    }
    #pragma unroll
    for (int j = 0; j < 4; j++) {
        int e = tid + j * 256; int row = e >> 3, seg = e & 7;
        cp16(smem_u32p(smu + 4608 + row * PW + seg * 4), g_BTh + (size_t)(l0 + row) * NB + seg * 8);
    }
    cp_commit();
    cp_wait<0>();
    __syncthreads();

    // -------- per-lane ldmatrix base addresses --------
    const int arow   = lane & 15;
    const int acol16 = (lane >> 4) & 1;
    const uint32_t aHi = smem_u32p(smu +        (rw + arow) * PW) + acol16 * 16;
    const uint32_t aLo = smem_u32p(smu + 2304 + (rw + arow) * PW) + acol16 * 16;
    const int brow   = lane & 7;
    const int bcol16 = (lane >> 3) & 1;
    const int bpair  = (lane >> 4) & 1;
    const uint32_t bHi = smem_u32p(smu + 4608 + (lw + bpair * 8 + brow) * PW) + bcol16 * 16;

    float acc[8][4];
    #pragma unroll
    for (int i = 0; i < 8; i++)
        #pragma unroll
        for (int j = 0; j < 4; j++) acc[i][j] = 0.f;

    #pragma unroll
    for (int ks = 0; ks < 4; ks++) {
        const int kb = ks * 32;
        uint32_t ah[2][4], al[2][4], bh[2][4];
        #pragma unroll
        for (int mt = 0; mt < 2; mt++) {
            ldsm_x4(ah[mt], aHi + mt * (16 * PW * 4) + kb);
            ldsm_x4(al[mt], aLo + mt * (16 * PW * 4) + kb);
        }
        #pragma unroll
        for (int p = 0; p < 2; p++)
            ldsm_x4(bh[p], bHi + p * (16 * PW * 4) + kb);
        #pragma unroll
        for (int mt = 0; mt < 2; mt++)
            #pragma unroll
            for (int nt = 0; nt < 4; nt++) {
                const int p = nt >> 1, o = (nt & 1) * 2;
                mma16(acc[mt * 4 + nt], ah[mt], &bh[p][o]);
                mma16(acc[mt * 4 + nt], al[mt], &bh[p][o]);
            }
    }

    // -------- epilogue: attn -> smem staging, then coalesced out = x + attn --------
    __syncthreads();                      // everyone done reading W/BTh smem
    float* smf = (float*)smu;
    #pragma unroll
    for (int mt = 0; mt < 2; mt++)
        #pragma unroll
        for (int nt = 0; nt < 4; nt++) {
            int row = rw + mt * 16 + g;
            int col = lw + nt * 8 + 2 * tig;
            const float* c = acc[mt * 4 + nt];
            *(float2*)(smf + row * SE + col)       = make_float2(c[0], c[1]);
            *(float2*)(smf + (row + 8) * SE + col) = make_float2(c[2], c[3]);
        }
    __syncthreads();

    #pragma unroll
    for (int pass = 0; pass < 8; pass++) {
        int row = pass * 8 + warp;
        int col = lane * 4;
        float4 a = *(const float4*)(smf + row * SE + col);
        size_t gi = (size_t)(r0 + row) * LVAL + l0 + col;
        float4 xv = *(const float4*)(x + gi);
        *(float4*)(out + gi) =
            make_float4(xv.x + a.x, xv.y + a.y, xv.z + a.z, xv.w + a.w);
    }
}

// ---------------- launch ----------------
extern "C" void kernel_launch(void* const* d_in, const int* in_sizes, int n_in,
                              void* d_out, int out_size) {
    const float* x = (const float*)d_in[0];
    float* out = (float*)d_out;
    (void)in_sizes; (void)n_in; (void)out_size;

    static bool attr_done = false;
    if (!attr_done) {
        cudaFuncSetAttribute(k2_proj, cudaFuncAttributeMaxDynamicSharedMemorySize, K2_SMEM_BYTES);
        cudaFuncSetAttribute(k4_attn, cudaFuncAttributeMaxDynamicSharedMemorySize, K4_SMEM_BYTES);
        attr_done = true;
    }

    k1_build<<<(NB * LVAL + 255) / 256, 256>>>();
    k2_proj<<<dim3(NROWS / 64, KSPLIT), 256, K2_SMEM_BYTES>>>(x);
    k3_softmax<<<NROWS / 8, 256>>>();
    k4_attn<<<dim3(LVAL / 128, NROWS / 64), 256, K4_SMEM_BYTES>>>(x, out);
}

// round 16
// speedup vs baseline: 1.0210x; 1.0210x over previous
#include <cuda_runtime.h>
#include <cuda_fp16.h>
#include <cstdint>

#define LVAL 4096
#define NB 64
#define NROWS 16384            // 32*512
#define PW 36                  // padded row stride in u32 words (32 data words + 4 pad)
#define RADIUS 0.9
#define KSPLIT 8

// ---------------- device globals (no allocs allowed) ----------------
__device__ __half g_Bh [NB * LVAL];    // Blaschke hi split, [n][l] l-contig
__device__ __half g_Bl [NB * LVAL];    // lo split
__device__ __half g_BTh[LVAL * NB];    // transposed (plain fp16 B for attn GEMM)
__device__ float  g_proj[KSPLIT * NROWS * NB];   // split-K partial projections
__device__ __half g_W0[NROWS * NB];    // softmax weights hi split, [row][n]
__device__ __half g_W1[NROWS * NB];    // lo split

// ---------------- helpers ----------------
__device__ __forceinline__ unsigned smem_u32p(const void* p) {
    return (unsigned)__cvta_generic_to_shared(p);
}
__device__ __forceinline__ void cp16(unsigned dst, const void* src) {
    asm volatile("cp.async.ca.shared.global [%0], [%1], 16;\n" :: "r"(dst), "l"(src));
}
__device__ __forceinline__ void cp_commit() {
    asm volatile("cp.async.commit_group;\n" ::: "memory");
}
template <int N>
__device__ __forceinline__ void cp_wait() {
    asm volatile("cp.async.wait_group %0;\n" :: "n"(N) : "memory");
}
__device__ __forceinline__ uint32_t packh(__half a, __half b) {
    __half2 h = __halves2half2(a, b);
    return *reinterpret_cast<uint32_t*>(&h);
}
__device__ __forceinline__ uint32_t pack_rn(float a, float b) {
    return packh(__float2half_rn(a), __float2half_rn(b));
}
__device__ __forceinline__ uint32_t h2u(__half2 h) {
    return *reinterpret_cast<uint32_t*>(&h);
}

// D(16x8) += A(16x16) * B(16x8), fp16 inputs, fp32 accum
__device__ __forceinline__ void mma16(float* c, const uint32_t* a, const uint32_t* b) {
    asm volatile(
        "mma.sync.aligned.m16n8k16.row.col.f32.f16.f16.f32 "
        "{%0,%1,%2,%3}, {%4,%5,%6,%7}, {%8,%9}, {%0,%1,%2,%3};\n"
        : "+f"(c[0]), "+f"(c[1]), "+f"(c[2]), "+f"(c[3])
        : "r"(a[0]), "r"(a[1]), "r"(a[2]), "r"(a[3]),
          "r"(b[0]), "r"(b[1]));
}

__device__ __forceinline__ void ldsm_x4(uint32_t* r, uint32_t addr) {
    asm volatile("ldmatrix.sync.aligned.m8n8.x4.shared.b16 {%0,%1,%2,%3}, [%4];"
        : "=r"(r[0]), "=r"(r[1]), "=r"(r[2]), "=r"(r[3]) : "r"(addr));
}

// ---------------- k1: build Blaschke basis + fp16 splits ----------------
__global__ void k1_build() {
    int idx = blockIdx.x * blockDim.x + threadIdx.x;
    if (idx >= NB * LVAL) return;
    int n = idx >> 12;
    int l = idx & 4095;
    const double TWO_PI = 6.283185307179586476925286766559;
    double theta = (double)n * (TWO_PI / 64.0);
    double t     = (double)l * (TWO_PI / 4095.0);   // linspace(0,2pi,4096) incl. endpoint
    float c = cosf((float)(t - theta));             // arg exact in double, cos in fp32
    const float r = (float)RADIUS;
    float v = sqrtf(1.0f - r * r) * (1.0f - r * c) / (1.0f - 2.0f * r * c + r * r);
    __half h = __float2half_rn(v);
    __half lo = __float2half_rn(v - __half2float(h));
    g_Bh [n * LVAL + l] = h;
    g_Bl [n * LVAL + l] = lo;
    g_BTh[l * NB + n]   = h;
}

// ---------------- k2: proj slab GEMM  (split-K = 8, 128-row CTA, pipelined) ----
// CTA: 128 rows x 64 basis, K-slice 512, 8 chunks of 64, double-buffered.
// stage layout (u32 words): xh[0,4608) xl[4608,9216) bh[9216,11520) bl[11520,13824)
#define K2_STAGE 13824
#define K2_SMEM_BYTES (2 * K2_STAGE * 4)   // 110592

__global__ __launch_bounds__(256, 2) void k2_proj(const float* __restrict__ x) {
    extern __shared__ uint32_t smu[];
    const int tid = threadIdx.x, warp = tid >> 5, lane = tid & 31;
    const int g = lane >> 2, tig = lane & 3;
    const int r0 = blockIdx.x * 128;
    const int kslab = blockIdx.y * (LVAL / KSPLIT);   // 512
    const int rw = (warp & 3) * 32;      // warp x-row offset (A operand, m)
    const int nw = (warp >> 2) * 32;     // warp basis offset (B operand, n)
    const int quad = tid & 15, rloc = tid >> 4;

    const int arow   = lane & 15;
    const int acol16 = (lane >> 4) & 1;
    const int brow   = lane & 7;
    const int bcol16 = (lane >> 3) & 1;
    const int bpair  = (lane >> 4) & 1;

    float acc[8][4];
    #pragma unroll
    for (int i = 0; i < 8; i++)
        #pragma unroll
        for (int j = 0; j < 4; j++) acc[i][j] = 0.f;

    auto ldg_x = [&](int c, float4* xr) {
        const int kbase = kslab + c * 64;
        #pragma unroll
        for (int i = 0; i < 8; i++) {
            int row = rloc + i * 16;
            xr[i] = *(const float4*)(x + (size_t)(r0 + row) * LVAL + kbase + quad * 4);
        }
    };
    // packed hi/lo split: 4x F2FP.f16x2, 2x unpack, 4 FADD per float4
    auto cvt_sts_x = [&](int c, const float4* xr) {
        uint32_t* b = smu + (c & 1) * K2_STAGE;
        #pragma unroll
        for (int i = 0; i < 8; i++) {
            int row = rloc + i * 16;
            const float4 v = xr[i];
            __half2 h01 = __floats2half2_rn(v.x, v.y);
            __half2 h23 = __floats2half2_rn(v.z, v.w);
            float2 f01 = __half22float2(h01);
            float2 f23 = __half22float2(h23);
            __half2 l01 = __floats2half2_rn(v.x - f01.x, v.y - f01.y);
            __half2 l23 = __floats2half2_rn(v.z - f23.x, v.w - f23.y);
            *(uint2*)(b + row * PW + quad * 2)        = make_uint2(h2u(h01), h2u(h23));
            *(uint2*)(b + 4608 + row * PW + quad * 2) = make_uint2(h2u(l01), h2u(l23));
        }
    };
    auto cp_B = [&](int c) {
        uint32_t* b = smu + (c & 1) * K2_STAGE;
        const int kbase = kslab + c * 64;
        #pragma unroll
        for (int j = 0; j < 2; j++) {
            int e = tid + j * 256; int n = e >> 3, seg = e & 7;
            cp16(smem_u32p(b + 9216  + n * PW + seg * 4),
                 g_Bh + (size_t)n * LVAL + kbase + seg * 8);
            cp16(smem_u32p(b + 11520 + n * PW + seg * 4),
                 g_Bl + (size_t)n * LVAL + kbase + seg * 8);
        }
        cp_commit();
    };

    float4 xr[8];
    // prologue: B0 in flight; x0 converted; x1 loaded into regs
    cp_B(0);
    ldg_x(0, xr);
    cvt_sts_x(0, xr);
    ldg_x(1, xr);

    for (int c = 0; c < KSPLIT; c++) {
        cp_wait<0>();          // B_c landed
        __syncthreads();       // orders STS x_c + frees buffer (c+1)&1
        if (c + 1 < KSPLIT) cp_B(c + 1);   // overlaps mma(c)

        const uint32_t* buf = smu + (c & 1) * K2_STAGE;
        const uint32_t aHi = smem_u32p(buf +        (rw + arow) * PW) + acol16 * 16;
        const uint32_t aLo = smem_u32p(buf + 4608 + (rw + arow) * PW) + acol16 * 16;
        const uint32_t bHi = smem_u32p(buf + 9216  + (nw + bpair * 8 + brow) * PW) + bcol16 * 16;
        const uint32_t bLo = smem_u32p(buf + 11520 + (nw + bpair * 8 + brow) * PW) + bcol16 * 16;

        #pragma unroll
        for (int ks = 0; ks < 4; ks++) {
            const int kb = ks * 32;
            uint32_t ah[2][4], al[2][4], bh[2][4], bl[2][4];
            #pragma unroll
            for (int mt = 0; mt < 2; mt++) {
                ldsm_x4(ah[mt], aHi + mt * (16 * PW * 4) + kb);
                ldsm_x4(al[mt], aLo + mt * (16 * PW * 4) + kb);
            }
            #pragma unroll
            for (int p = 0; p < 2; p++) {
                ldsm_x4(bh[p], bHi + p * (16 * PW * 4) + kb);
                ldsm_x4(bl[p], bLo + p * (16 * PW * 4) + kb);
            }
            #pragma unroll
            for (int mt = 0; mt < 2; mt++)
                #pragma unroll
                for (int nt = 0; nt < 4; nt++) {
                    const int p = nt >> 1, o = (nt & 1) * 2;
                    mma16(acc[mt * 4 + nt], ah[mt], &bh[p][o]);
                    mma16(acc[mt * 4 + nt], ah[mt], &bl[p][o]);
                    mma16(acc[mt * 4 + nt], al[mt], &bh[p][o]);
                }
        }

        if (c + 1 < KSPLIT) {
            cvt_sts_x(c + 1, xr);                   // regs loaded last iteration
            if (c + 2 < KSPLIT) ldg_x(c + 2, xr);   // hidden behind next mma
        }
    }

    float* slab = g_proj + (size_t)blockIdx.y * (NROWS * NB);
    #pragma unroll
    for (int mt = 0; mt < 2; mt++)
        #pragma unroll
        for (int nt = 0; nt < 4; nt++) {
            int col = nw + nt * 8 + 2 * tig;
            int row = r0 + rw + mt * 16 + g;
            const float* cacc = acc[mt * 4 + nt];
            *(float2*)(slab + (size_t)row * NB + col)       = make_float2(cacc[0], cacc[1]);
            *(float2*)(slab + (size_t)(row + 8) * NB + col) = make_float2(cacc[2], cacc[3]);
        }
}

// ---------------- k3: reduce slabs + softmax(|.|) + fp16 W split ----------------
__global__ __launch_bounds__(256) void k3_softmax() {
    const int warp = threadIdx.x >> 5, lane = threadIdx.x & 31;
    const int row = blockIdx.x * 8 + warp;
    const size_t base = (size_t)row * NB + 2 * lane;
    float p0 = 0.f, p1 = 0.f;
    #pragma unroll
    for (int s = 0; s < KSPLIT; s++) {
        float2 v = *(const float2*)(g_proj + (size_t)s * (NROWS * NB) + base);
        p0 += v.x; p1 += v.y;
    }
    float a0 = fabsf(p0), a1 = fabsf(p1);
    float m = fmaxf(a0, a1);
    #pragma unroll
    for (int o = 16; o > 0; o >>= 1) m = fmaxf(m, __shfl_xor_sync(0xffffffffu, m, o));
    float e0 = __expf(a0 - m), e1 = __expf(a1 - m);
    float s = e0 + e1;
    #pragma unroll
    for (int o = 16; o > 0; o >>= 1) s += __shfl_xor_sync(0xffffffffu, s, o);
    float inv = 1.0f / s;
    float w0 = e0 * inv, w1 = e1 * inv;
    __half h0 = __float2half_rn(w0), h1 = __float2half_rn(w1);
    *(uint32_t*)&g_W0[base] = packh(h0, h1);
    *(uint32_t*)&g_W1[base] = pack_rn(w0 - __half2float(h0), w1 - __half2float(h1));
}

// ---------------- k4: out = x + W*B  (64 rows x 128 l per CTA, 2-term) ----------------
// attn = (Wh + Wl) * Bh ; W split exact, B plain fp16 (validated rel_err 1.28e-4, 91.5us)
// smem (u32 words): Wh[0,2304) Wl[2304,4608) BTh[4608,9216)
// epilogue reuses smem as fp32 attn staging [64][132] (8448 words < 9216)
#define K4_SMEM_WORDS 9216
#define K4_SMEM_BYTES (K4_SMEM_WORDS * 4)   // 36864
#define SE 132                 // epilogue staging stride (floats)

__global__ __launch_bounds__(256, 4) void k4_attn(
    const float* __restrict__ x, float* __restrict__ out)
{
    extern __shared__ uint32_t smu[];
    const int tid = threadIdx.x, warp = tid >> 5, lane = tid & 31;
    const int g = lane >> 2, tig = lane & 3;
    const int r0 = blockIdx.y * 64;
    const int l0 = blockIdx.x * 128;
    const int rw = (warp & 1) * 32;      // warp row offset (2 groups of 32)
    const int lw = (warp >> 1) * 32;     // warp l offset   (4 groups of 32)

    // -------- stage W hi/lo (64 rows) and BTh (128 rows) via cp.async --------
    #pragma unroll
    for (int j = 0; j < 2; j++) {
        int e = tid + j * 256; int row = e >> 3, seg = e & 7;
        cp16(smem_u32p(smu + 0    + row * PW + seg * 4), g_W0 + (size_t)(r0 + row) * NB + seg * 8);
        cp16(smem_u32p(smu + 2304 + row * PW + seg * 4), g_W1 + (size_t)(r0 + row) * NB + seg * 8);
    }
    #pragma unroll
    for (int j = 0; j < 4; j++) {
        int e = tid + j * 256; int row = e >> 3, seg = e & 7;
        cp16(smem_u32p(smu + 4608 + row * PW + seg * 4), g_BTh + (size_t)(l0 + row) * NB + seg * 8);
    }
    cp_commit();
    cp_wait<0>();
    __syncthreads();

    // -------- per-lane ldmatrix base addresses --------
    const int arow   = lane & 15;
    const int acol16 = (lane >> 4) & 1;
    const uint32_t aHi = smem_u32p(smu +        (rw + arow) * PW) + acol16 * 16;
    const uint32_t aLo = smem_u32p(smu + 2304 + (rw + arow) * PW) + acol16 * 16;
    const int brow   = lane & 7;
    const int bcol16 = (lane >> 3) & 1;
    const int bpair  = (lane >> 4) & 1;
    const uint32_t bHi = smem_u32p(smu + 4608 + (lw + bpair * 8 + brow) * PW) + bcol16 * 16;

    float acc[8][4];
    #pragma unroll
    for (int i = 0; i < 8; i++)
        #pragma unroll
        for (int j = 0; j < 4; j++) acc[i][j] = 0.f;

    #pragma unroll
    for (int ks = 0; ks < 4; ks++) {
        const int kb = ks * 32;
        uint32_t ah[2][4], al[2][4], bh[2][4];
        #pragma unroll
        for (int mt = 0; mt < 2; mt++) {
            ldsm_x4(ah[mt], aHi + mt * (16 * PW * 4) + kb);
            ldsm_x4(al[mt], aLo + mt * (16 * PW * 4) + kb);
        }
        #pragma unroll
        for (int p = 0; p < 2; p++)
            ldsm_x4(bh[p], bHi + p * (16 * PW * 4) + kb);
        #pragma unroll
        for (int mt = 0; mt < 2; mt++)
            #pragma unroll
            for (int nt = 0; nt < 4; nt++) {
                const int p = nt >> 1, o = (nt & 1) * 2;
                mma16(acc[mt * 4 + nt], ah[mt], &bh[p][o]);
                mma16(acc[mt * 4 + nt], al[mt], &bh[p][o]);
            }
    }

    // -------- epilogue: attn -> smem staging, then coalesced out = x + attn --------
    __syncthreads();                      // everyone done reading W/BTh smem
    float* smf = (float*)smu;
    #pragma unroll
    for (int mt = 0; mt < 2; mt++)
        #pragma unroll
        for (int nt = 0; nt < 4; nt++) {
            int row = rw + mt * 16 + g;
            int col = lw + nt * 8 + 2 * tig;
            const float* c = acc[mt * 4 + nt];
            *(float2*)(smf + row * SE + col)       = make_float2(c[0], c[1]);
            *(float2*)(smf + (row + 8) * SE + col) = make_float2(c[2], c[3]);
        }
    __syncthreads();

    #pragma unroll
    for (int pass = 0; pass < 8; pass++) {
        int row = pass * 8 + warp;
        int col = lane * 4;
        float4 a = *(const float4*)(smf + row * SE + col);
        size_t gi = (size_t)(r0 + row) * LVAL + l0 + col;
        float4 xv = *(const float4*)(x + gi);
        *(float4*)(out + gi) =
            make_float4(xv.x + a.x, xv.y + a.y, xv.z + a.z, xv.w + a.w);
    }
}

// ---------------- launch ----------------
extern "C" void kernel_launch(void* const* d_in, const int* in_sizes, int n_in,
                              void* d_out, int out_size) {
    const float* x = (const float*)d_in[0];
    float* out = (float*)d_out;
    (void)in_sizes; (void)n_in; (void)out_size;

    static bool attr_done = false;
    if (!attr_done) {
        cudaFuncSetAttribute(k2_proj, cudaFuncAttributeMaxDynamicSharedMemorySize, K2_SMEM_BYTES);
        cudaFuncSetAttribute(k4_attn, cudaFuncAttributeMaxDynamicSharedMemorySize, K4_SMEM_BYTES);
        attr_done = true;
    }

    k1_build<<<(NB * LVAL + 255) / 256, 256>>>();
    k2_proj<<<dim3(NROWS / 128, KSPLIT), 256, K2_SMEM_BYTES>>>(x);
    k3_softmax<<<NROWS / 8, 256>>>();
    k4_attn<<<dim3(LVAL / 128, NROWS / 64), 256, K4_SMEM_BYTES>>>(x, out);
}

// round 17
// speedup vs baseline: 1.1207x; 1.0977x over previous
#include <cuda_runtime.h>
#include <cuda_fp16.h>
#include <cstdint>

#define LVAL 4096
#define NB 64
#define NROWS 16384            // 32*512
#define PW 36                  // k4 stage stride in u32 words (32 data + 4 pad)
#define RADIUS 0.9
#define KSPLIT 8

// ---------------- device globals (no allocs allowed) ----------------
__device__ __half g_Bh [NB * LVAL];    // Blaschke hi split, [n][l] l-contig
__device__ __half g_Bl [NB * LVAL];    // lo split
__device__ __half g_BTh[LVAL * NB];    // transposed (plain fp16 B for attn GEMM)
__device__ float  g_proj[KSPLIT * NROWS * NB];   // split-K partial projections
__device__ __half g_W0[NROWS * NB];    // softmax weights hi split, [row][n]
__device__ __half g_W1[NROWS * NB];    // lo split

// ---------------- helpers ----------------
__device__ __forceinline__ unsigned smem_u32p(const void* p) {
    return (unsigned)__cvta_generic_to_shared(p);
}
__device__ __forceinline__ void cp16(unsigned dst, const void* src) {
    asm volatile("cp.async.ca.shared.global [%0], [%1], 16;\n" :: "r"(dst), "l"(src));
}
__device__ __forceinline__ void cp_commit() {
    asm volatile("cp.async.commit_group;\n" ::: "memory");
}
template <int N>
__device__ __forceinline__ void cp_wait() {
    asm volatile("cp.async.wait_group %0;\n" :: "n"(N) : "memory");
}
__device__ __forceinline__ uint32_t packh(__half a, __half b) {
    __half2 h = __halves2half2(a, b);
    return *reinterpret_cast<uint32_t*>(&h);
}
__device__ __forceinline__ uint32_t pack_rn(float a, float b) {
    return packh(__float2half_rn(a), __float2half_rn(b));
}
__device__ __forceinline__ uint32_t h2u(__half2 h) {
    return *reinterpret_cast<uint32_t*>(&h);
}

// D(16x8) += A(16x16) * B(16x8), fp16 inputs, fp32 accum
__device__ __forceinline__ void mma16(float* c, const uint32_t* a, const uint32_t* b) {
    asm volatile(
        "mma.sync.aligned.m16n8k16.row.col.f32.f16.f16.f32 "
        "{%0,%1,%2,%3}, {%4,%5,%6,%7}, {%8,%9}, {%0,%1,%2,%3};\n"
        : "+f"(c[0]), "+f"(c[1]), "+f"(c[2]), "+f"(c[3])
        : "r"(a[0]), "r"(a[1]), "r"(a[2]), "r"(a[3]),
          "r"(b[0]), "r"(b[1]));
}

__device__ __forceinline__ void ldsm_x4(uint32_t* r, uint32_t addr) {
    asm volatile("ldmatrix.sync.aligned.m8n8.x4.shared.b16 {%0,%1,%2,%3}, [%4];"
        : "=r"(r[0]), "=r"(r[1]), "=r"(r[2]), "=r"(r[3]) : "r"(addr));
}

// ---------------- k1: build Blaschke basis + fp16 splits ----------------
__global__ void k1_build() {
    int idx = blockIdx.x * blockDim.x + threadIdx.x;
    if (idx >= NB * LVAL) return;
    int n = idx >> 12;
    int l = idx & 4095;
    const double TWO_PI = 6.283185307179586476925286766559;
    double theta = (double)n * (TWO_PI / 64.0);
    double t     = (double)l * (TWO_PI / 4095.0);   // linspace(0,2pi,4096) incl. endpoint
    float c = cosf((float)(t - theta));             // arg exact in double, cos in fp32
    const float r = (float)RADIUS;
    float v = sqrtf(1.0f - r * r) * (1.0f - r * c) / (1.0f - 2.0f * r * c + r * r);
    __half h = __float2half_rn(v);
    __half lo = __float2half_rn(v - __half2float(h));
    g_Bh [n * LVAL + l] = h;
    g_Bl [n * LVAL + l] = lo;
    g_BTh[l * NB + n]   = h;
}

// ---------------- k2: proj slab GEMM  (split-K=8, 128-row CTA, KC=32, occ 3) ----
// CTA: 128 rows x 64 basis, K-slice 512 in 16 chunks of 32, double-buffered, pipelined.
// stage layout (u32 words, PW2=20/row = 16 data + 4 pad, conflict-free for ldsm):
//   xh[0,2560) xl[2560,5120) bh[5120,6400) bl[6400,7680)
#define PW2 20
#define K2_STAGE 7680
#define K2_SMEM_BYTES (2 * K2_STAGE * 4)   // 61440 -> 3 CTAs/SM

__global__ __launch_bounds__(256, 3) void k2_proj(const float* __restrict__ x) {
    extern __shared__ uint32_t smu[];
    const int tid = threadIdx.x, warp = tid >> 5, lane = tid & 31;
    const int g = lane >> 2, tig = lane & 3;
    const int r0 = blockIdx.x * 128;
    const int kslab = blockIdx.y * (LVAL / KSPLIT);   // 512
    const int rw = (warp & 3) * 32;      // warp x-row offset (A operand, m)
    const int nw = (warp >> 2) * 32;     // warp basis offset (B operand, n)
    const int quad = tid & 7, rloc = tid >> 3;   // x loads: 8 float4 per row

    const int arow   = lane & 15;
    const int acol16 = (lane >> 4) & 1;
    const int brow   = lane & 7;
    const int bcol16 = (lane >> 3) & 1;
    const int bpair  = (lane >> 4) & 1;

    float acc[8][4];
    #pragma unroll
    for (int i = 0; i < 8; i++)
        #pragma unroll
        for (int j = 0; j < 4; j++) acc[i][j] = 0.f;

    auto ldg_x = [&](int c, float4* xr) {
        const int kbase = kslab + c * 32;
        #pragma unroll
        for (int i = 0; i < 4; i++) {
            int row = rloc + i * 32;
            xr[i] = *(const float4*)(x + (size_t)(r0 + row) * LVAL + kbase + quad * 4);
        }
    };
    auto cvt_sts_x = [&](int c, const float4* xr) {
        uint32_t* b = smu + (c & 1) * K2_STAGE;
        #pragma unroll
        for (int i = 0; i < 4; i++) {
            int row = rloc + i * 32;
            const float4 v = xr[i];
            __half2 h01 = __floats2half2_rn(v.x, v.y);
            __half2 h23 = __floats2half2_rn(v.z, v.w);
            float2 f01 = __half22float2(h01);
            float2 f23 = __half22float2(h23);
            __half2 l01 = __floats2half2_rn(v.x - f01.x, v.y - f01.y);
            __half2 l23 = __floats2half2_rn(v.z - f23.x, v.w - f23.y);
            *(uint2*)(b + row * PW2 + quad * 2)        = make_uint2(h2u(h01), h2u(h23));
            *(uint2*)(b + 2560 + row * PW2 + quad * 2) = make_uint2(h2u(l01), h2u(l23));
        }
    };
    auto cp_B = [&](int c) {
        uint32_t* b = smu + (c & 1) * K2_STAGE;
        const int kbase = kslab + c * 32;
        int n = tid >> 2, seg = tid & 3;   // 64 rows x 4 chunks of 16B
        cp16(smem_u32p(b + 5120 + n * PW2 + seg * 4),
             g_Bh + (size_t)n * LVAL + kbase + seg * 8);
        cp16(smem_u32p(b + 6400 + n * PW2 + seg * 4),
             g_Bl + (size_t)n * LVAL + kbase + seg * 8);
        cp_commit();
    };

    float4 xr[4];
    // prologue: B0 in flight; x0 converted; x1 loaded into regs
    cp_B(0);
    ldg_x(0, xr);
    cvt_sts_x(0, xr);
    ldg_x(1, xr);

    const int NCH = 16;
    for (int c = 0; c < NCH; c++) {
        cp_wait<0>();          // B_c landed
        __syncthreads();       // orders STS x_c + frees buffer (c+1)&1
        if (c + 1 < NCH) cp_B(c + 1);   // overlaps mma(c)

        const uint32_t* buf = smu + (c & 1) * K2_STAGE;
        const uint32_t aHi = smem_u32p(buf +        (rw + arow) * PW2) + acol16 * 16;
        const uint32_t aLo = smem_u32p(buf + 2560 + (rw + arow) * PW2) + acol16 * 16;
        const uint32_t bHi = smem_u32p(buf + 5120 + (nw + bpair * 8 + brow) * PW2) + bcol16 * 16;
        const uint32_t bLo = smem_u32p(buf + 6400 + (nw + bpair * 8 + brow) * PW2) + bcol16 * 16;

        #pragma unroll
        for (int ks = 0; ks < 2; ks++) {
            const int kb = ks * 32;   // 16 halfs per k-step
            uint32_t ah[2][4], al[2][4], bh[2][4], bl[2][4];
            #pragma unroll
            for (int mt = 0; mt < 2; mt++) {
                ldsm_x4(ah[mt], aHi + mt * (16 * PW2 * 4) + kb);
                ldsm_x4(al[mt], aLo + mt * (16 * PW2 * 4) + kb);
            }
            #pragma unroll
            for (int p = 0; p < 2; p++) {
                ldsm_x4(bh[p], bHi + p * (16 * PW2 * 4) + kb);
                ldsm_x4(bl[p], bLo + p * (16 * PW2 * 4) + kb);
            }
            #pragma unroll
            for (int mt = 0; mt < 2; mt++)
                #pragma unroll
                for (int nt = 0; nt < 4; nt++) {
                    const int p = nt >> 1, o = (nt & 1) * 2;
                    mma16(acc[mt * 4 + nt], ah[mt], &bh[p][o]);
                    mma16(acc[mt * 4 + nt], ah[mt], &bl[p][o]);
                    mma16(acc[mt * 4 + nt], al[mt], &bh[p][o]);
                }
        }

        if (c + 1 < NCH) {
            cvt_sts_x(c + 1, xr);                // regs loaded last iteration
            if (c + 2 < NCH) ldg_x(c + 2, xr);   // hidden behind next mma
        }
    }

    float* slab = g_proj + (size_t)blockIdx.y * (NROWS * NB);
    #pragma unroll
    for (int mt = 0; mt < 2; mt++)
        #pragma unroll
        for (int nt = 0; nt < 4; nt++) {
            int col = nw + nt * 8 + 2 * tig;
            int row = r0 + rw + mt * 16 + g;
            const float* cacc = acc[mt * 4 + nt];
            *(float2*)(slab + (size_t)row * NB + col)       = make_float2(cacc[0], cacc[1]);
            *(float2*)(slab + (size_t)(row + 8) * NB + col) = make_float2(cacc[2], cacc[3]);
        }
}

// ---------------- k3: reduce slabs + softmax(|.|) + fp16 W split ----------------
__global__ __launch_bounds__(256) void k3_softmax() {
    const int warp = threadIdx.x >> 5, lane = threadIdx.x & 31;
    const int row = blockIdx.x * 8 + warp;
    const size_t base = (size_t)row * NB + 2 * lane;
    float p0 = 0.f, p1 = 0.f;
    #pragma unroll
    for (int s = 0; s < KSPLIT; s++) {
        float2 v = *(const float2*)(g_proj + (size_t)s * (NROWS * NB) + base);
        p0 += v.x; p1 += v.y;
    }
    float a0 = fabsf(p0), a1 = fabsf(p1);
    float m = fmaxf(a0, a1);
    #pragma unroll
    for (int o = 16; o > 0; o >>= 1) m = fmaxf(m, __shfl_xor_sync(0xffffffffu, m, o));
    float e0 = __expf(a0 - m), e1 = __expf(a1 - m);
    float s = e0 + e1;
    #pragma unroll
    for (int o = 16; o > 0; o >>= 1) s += __shfl_xor_sync(0xffffffffu, s, o);
    float inv = 1.0f / s;
    float w0 = e0 * inv, w1 = e1 * inv;
    __half h0 = __float2half_rn(w0), h1 = __float2half_rn(w1);
    *(uint32_t*)&g_W0[base] = packh(h0, h1);
    *(uint32_t*)&g_W1[base] = pack_rn(w0 - __half2float(h0), w1 - __half2float(h1));
}

// ---------------- k4: out = x + W*B  (64 rows x 128 l per CTA, 2-term) ----------------
// attn = (Wh + Wl) * Bh ; W split exact, B plain fp16 (validated rel_err 1.28e-4, ~92us)
// smem (u32 words): Wh[0,2304) Wl[2304,4608) BTh[4608,9216)
// epilogue reuses smem as fp32 attn staging [64][132] (8448 words < 9216)
#define K4_SMEM_WORDS 9216
#define K4_SMEM_BYTES (K4_SMEM_WORDS * 4)   // 36864
#define SE 132                 // epilogue staging stride (floats)

__global__ __launch_bounds__(256, 4) void k4_attn(
    const float* __restrict__ x, float* __restrict__ out)
{
    extern __shared__ uint32_t smu[];
    const int tid = threadIdx.x, warp = tid >> 5, lane = tid & 31;
    const int g = lane >> 2, tig = lane & 3;
    const int r0 = blockIdx.y * 64;
    const int l0 = blockIdx.x * 128;
    const int rw = (warp & 1) * 32;      // warp row offset (2 groups of 32)
    const int lw = (warp >> 1) * 32;     // warp l offset   (4 groups of 32)

    // -------- stage W hi/lo (64 rows) and BTh (128 rows) via cp.async --------
    #pragma unroll
    for (int j = 0; j < 2; j++) {
        int e = tid + j * 256; int row = e >> 3, seg = e & 7;
        cp16(smem_u32p(smu + 0    + row * PW + seg * 4), g_W0 + (size_t)(r0 + row) * NB + seg * 8);
        cp16(smem_u32p(smu + 2304 + row * PW + seg * 4), g_W1 + (size_t)(r0 + row) * NB + seg * 8);
    }
    #pragma unroll
    for (int j = 0; j < 4; j++) {
        int e = tid + j * 256; int row = e >> 3, seg = e & 7;
        cp16(smem_u32p(smu + 4608 + row * PW + seg * 4), g_BTh + (size_t)(l0 + row) * NB + seg * 8);
    }
    cp_commit();
    cp_wait<0>();
    __syncthreads();

    // -------- per-lane ldmatrix base addresses --------
    const int arow   = lane & 15;
    const int acol16 = (lane >> 4) & 1;
    const uint32_t aHi = smem_u32p(smu +        (rw + arow) * PW) + acol16 * 16;
    const uint32_t aLo = smem_u32p(smu + 2304 + (rw + arow) * PW) + acol16 * 16;
    const int brow   = lane & 7;
    const int bcol16 = (lane >> 3) & 1;
    const int bpair  = (lane >> 4) & 1;
    const uint32_t bHi = smem_u32p(smu + 4608 + (lw + bpair * 8 + brow) * PW) + bcol16 * 16;

    float acc[8][4];
    #pragma unroll
    for (int i = 0; i < 8; i++)
        #pragma unroll
        for (int j = 0; j < 4; j++) acc[i][j] = 0.f;

    #pragma unroll
    for (int ks = 0; ks < 4; ks++) {
        const int kb = ks * 32;
        uint32_t ah[2][4], al[2][4], bh[2][4];
        #pragma unroll
        for (int mt = 0; mt < 2; mt++) {
            ldsm_x4(ah[mt], aHi + mt * (16 * PW * 4) + kb);
            ldsm_x4(al[mt], aLo + mt * (16 * PW * 4) + kb);
        }
        #pragma unroll
        for (int p = 0; p < 2; p++)
            ldsm_x4(bh[p], bHi + p * (16 * PW * 4) + kb);
        #pragma unroll
        for (int mt = 0; mt < 2; mt++)
            #pragma unroll
            for (int nt = 0; nt < 4; nt++) {
                const int p = nt >> 1, o = (nt & 1) * 2;
                mma16(acc[mt * 4 + nt], ah[mt], &bh[p][o]);
                mma16(acc[mt * 4 + nt], al[mt], &bh[p][o]);
            }
    }

    // -------- epilogue: attn -> smem staging, then coalesced out = x + attn --------
    __syncthreads();                      // everyone done reading W/BTh smem
    float* smf = (float*)smu;
    #pragma unroll
    for (int mt = 0; mt < 2; mt++)
        #pragma unroll
        for (int nt = 0; nt < 4; nt++) {
            int row = rw + mt * 16 + g;
            int col = lw + nt * 8 + 2 * tig;
            const float* c = acc[mt * 4 + nt];
            *(float2*)(smf + row * SE + col)       = make_float2(c[0], c[1]);
            *(float2*)(smf + (row + 8) * SE + col) = make_float2(c[2], c[3]);
        }
    __syncthreads();

    #pragma unroll
    for (int pass = 0; pass < 8; pass++) {
        int row = pass * 8 + warp;
        int col = lane * 4;
        float4 a = *(const float4*)(smf + row * SE + col);
        size_t gi = (size_t)(r0 + row) * LVAL + l0 + col;
        float4 xv = *(const float4*)(x + gi);
        *(float4*)(out + gi) =
            make_float4(xv.x + a.x, xv.y + a.y, xv.z + a.z, xv.w + a.w);
    }
}

// ---------------- launch ----------------
extern "C" void kernel_launch(void* const* d_in, const int* in_sizes, int n_in,
                              void* d_out, int out_size) {
    const float* x = (const float*)d_in[0];
    float* out = (float*)d_out;
    (void)in_sizes; (void)n_in; (void)out_size;

    static bool attr_done = false;
    if (!attr_done) {
        cudaFuncSetAttribute(k2_proj, cudaFuncAttributeMaxDynamicSharedMemorySize, K2_SMEM_BYTES);
        cudaFuncSetAttribute(k4_attn, cudaFuncAttributeMaxDynamicSharedMemorySize, K4_SMEM_BYTES);
        attr_done = true;
    }

    k1_build<<<(NB * LVAL + 255) / 256, 256>>>();
    k2_proj<<<dim3(NROWS / 128, KSPLIT), 256, K2_SMEM_BYTES>>>(x);
    k3_softmax<<<NROWS / 8, 256>>>();
    k4_attn<<<dim3(LVAL / 128, NROWS / 64), 256, K4_SMEM_BYTES>>>(x, out);
}